// round 9
// baseline (speedup 1.0000x reference)
#include <cuda_runtime.h>
#include <math.h>

constexpr int Bn   = 64;
constexpr int Hn   = 512;
constexpr int Wn   = 512;
constexpr int NPTS = 512;
constexpr int HWn  = Hn * Wn;
constexpr int SLICES = 16;                  // blocks per image
constexpr int RB = Bn * SLICES;             // 1024 blocks
constexpr int TAPS_PER_IMG = NPTS * 9;      // 4608
constexpr int TAPS_PER_BLK = TAPS_PER_IMG / SLICES;   // 288
constexpr float SCALE = 0.25f;              // 512/2048
constexpr double CELL_AREA = 16.0;

// zero-initialized device scratch; restored every call for graph replay
__device__ float  g_target[(size_t)Bn * HWn];
__device__ double g_S[Bn], g_Q[Bn], g_T[Bn], g_A[Bn], g_C[Bn];
__device__ int    g_cnt[Bn * 32];           // per-image counters, 128B-padded
__device__ double g_acc[2];                 // (sum cnt, sum sp) over images
__device__ int    g_img_done;

__global__ void __launch_bounds__(256, 7)
k_all(const float* __restrict__ pred, const float* __restrict__ points,
      float* __restrict__ out) {
    const int tid = threadIdx.x;
    const int b = blockIdx.x >> 4;
    const int slice = blockIdx.x & (SLICES - 1);

    // ---- phase 1: stream S,Q over this block's slice (16 float4/thread) ----
    constexpr int CH = HWn / 4 / SLICES;    // 4096 float4 per block
    const float4* p = reinterpret_cast<const float4*>(pred)
                      + (size_t)b * (HWn / 4) + (size_t)slice * CH;
    float s = 0.f, q = 0.f;
    #pragma unroll
    for (int it = 0; it < 2; ++it) {
        float4 v[8];
        #pragma unroll
        for (int j = 0; j < 8; ++j)
            v[j] = p[(it * 8 + j) * 256 + tid];
        #pragma unroll
        for (int j = 0; j < 8; ++j) {
            s += (v[j].x + v[j].y) + (v[j].z + v[j].w);
            q += v[j].x * v[j].x + v[j].y * v[j].y
               + v[j].z * v[j].z + v[j].w * v[j].w;
        }
    }

    // ---- phase 2: 288 taps of image b (scatter + T + A + C telescoping) ----
    float tw = 0.f, ta = 0.f, tc = 0.f;
    const float* pb = pred + (size_t)b * HWn;
    float* tg = g_target + (size_t)b * HWn;
    {
        int i = tid;                         // 288 < 512: at most 2 per thread
        if (i < TAPS_PER_BLK + 0) { }        // (loop below handles 288 via stride)
    }
    for (int i = tid; i < TAPS_PER_BLK; i += 256) {
        int tapid = slice * TAPS_PER_BLK + i;
        int pt  = tapid / 9;
        int tap = tapid - pt * 9;
        float px = __ldg(&points[((size_t)b * NPTS + pt) * 2 + 0]);
        float py = __ldg(&points[((size_t)b * NPTS + pt) * 2 + 1]);
        int x = (int)fminf(fmaxf(px * SCALE, 0.f), (float)(Wn - 1));
        int y = (int)fminf(fmaxf(py * SCALE, 0.f), (float)(Hn - 1));
        int dy = tap / 3 - 1;
        int dx = tap - (tap / 3) * 3 - 1;
        int ny = y + dy, nx = x + dx;
        if ((unsigned)ny < (unsigned)Hn && (unsigned)nx < (unsigned)Wn) {
            int r2 = dy * dy + dx * dx;
            float w = (r2 == 0) ? 1.0f : (r2 == 1 ? 0.60653066f : 0.49306869f);
            int idx = ny * Wn + nx;
            float old = atomicAdd(&tg[idx], w);
            tc += w * (2.f * old + w);       // (old+w)^2 - old^2
            ta += w * __ldg(&pb[idx]);
            tw += w;
        }
    }

    // ---- block reduce 5 accumulators (whole block shares image b) ----
    #pragma unroll
    for (int o = 16; o; o >>= 1) {
        s  += __shfl_down_sync(0xffffffffu, s,  o);
        q  += __shfl_down_sync(0xffffffffu, q,  o);
        tw += __shfl_down_sync(0xffffffffu, tw, o);
        ta += __shfl_down_sync(0xffffffffu, ta, o);
        tc += __shfl_down_sync(0xffffffffu, tc, o);
    }
    __shared__ float sh[5][8];
    int lane = tid & 31, wid = tid >> 5;
    if (lane == 0) {
        sh[0][wid] = s; sh[1][wid] = q; sh[2][wid] = tw;
        sh[3][wid] = ta; sh[4][wid] = tc;
    }
    __syncthreads();
    if (tid == 0) {
        float S = 0.f, Q = 0.f, Tw = 0.f, Ta = 0.f, Tc = 0.f;
        #pragma unroll
        for (int j = 0; j < 8; ++j) {
            S += sh[0][j]; Q += sh[1][j]; Tw += sh[2][j];
            Ta += sh[3][j]; Tc += sh[4][j];
        }
        atomicAdd(&g_S[b], (double)S);
        atomicAdd(&g_Q[b], (double)Q);
        atomicAdd(&g_T[b], (double)Tw);
        atomicAdd(&g_A[b], (double)Ta);
        atomicAdd(&g_C[b], (double)Tc);
    }

    // ---- per-image completion: 16th block cleans + finalizes image b ----
    __shared__ int s_win;
    __threadfence();
    __syncthreads();
    if (tid == 0) {
        int old = atomicAdd(&g_cnt[b * 32], 1);
        s_win = (old == SLICES - 1) ? 1 : 0;
    }
    __syncthreads();
    if (!s_win) return;

    // winner: zero all touched cells of image b (1 tap per thread-slot)
    for (int i = tid; i < TAPS_PER_IMG; i += 256) {
        int pt  = i / 9;
        int tap = i - pt * 9;
        float px = __ldg(&points[((size_t)b * NPTS + pt) * 2 + 0]);
        float py = __ldg(&points[((size_t)b * NPTS + pt) * 2 + 1]);
        int x = (int)fminf(fmaxf(px * SCALE, 0.f), (float)(Wn - 1));
        int y = (int)fminf(fmaxf(py * SCALE, 0.f), (float)(Hn - 1));
        int dy = tap / 3 - 1;
        int dx = tap - (tap / 3) * 3 - 1;
        int ny = y + dy, nx = x + dx;
        if ((unsigned)ny < (unsigned)Hn && (unsigned)nx < (unsigned)Wn)
            tg[ny * Wn + nx] = 0.f;
    }

    if (tid == 0) {
        // volatile reads: all 16 blocks' atomics are L2-resident
        volatile double* vS = g_S; volatile double* vQ = g_Q;
        volatile double* vT = g_T; volatile double* vA = g_A;
        volatile double* vC = g_C;
        double S = vS[b], Q = vQ[b], T = vT[b], A = vA[b], C = vC[b];
        double cnt = fabs(S / CELL_AREA - (double)NPTS);
        double Sp = S + 1e-8;
        double sp = (Q / (Sp * Sp) - 2.0 * A / (Sp * T) + C / (T * T))
                    / (double)HWn;
        // reset for next graph replay
        g_S[b] = 0.0; g_Q[b] = 0.0; g_T[b] = 0.0; g_A[b] = 0.0; g_C[b] = 0.0;
        g_cnt[b * 32] = 0;
        atomicAdd(&g_acc[0], cnt);
        atomicAdd(&g_acc[1], sp);
        __threadfence();
        int old = atomicAdd(&g_img_done, 1);
        if (old == Bn - 1) {
            volatile double* va = g_acc;
            double count_loss = va[0] / (double)Bn;
            double spatial    = va[1] / (double)Bn;
            out[0] = (float)(2.5 * count_loss + 0.1 * spatial);
            out[1] = (float)count_loss;
            out[2] = (float)spatial;
            g_acc[0] = 0.0; g_acc[1] = 0.0;
            g_img_done = 0;
        }
    }
}

extern "C" void kernel_launch(void* const* d_in, const int* in_sizes, int n_in,
                              void* d_out, int out_size) {
    const float* pred   = (const float*)d_in[0];
    const float* points = (const float*)d_in[1];
    float* out = (float*)d_out;
    k_all<<<RB, 256>>>(pred, points, out);
}